// round 6
// baseline (speedup 1.0000x reference)
#include <cuda_runtime.h>
#include <cuda_bf16.h>
#include <cstdint>

// ---------------- problem constants ----------------
#define NPRED 1200
#define NTGT  256
#define NCLS  80
#define HW    128
#define SRC   256
#define PIX   16384
#define KTOT  16384
#define MROWS 2400      // rows 0..1199: X (logits), 1200..2399: sigmoid(X)

// ---------------- GEMM config (legacy mma.sync bf16, sm_100-safe) ----------------
#define BM     128
#define BN     256
#define BK     64                 // elements; 128B rows in smem
#define NKT    (KTOT / BK)        // 256 k-tiles
#define SPLITK 7
#define MT     19                 // ceil(2400/128)
#define ABYTES (BM * 128)         // 16 KB
#define BBYTES (BN * 128)         // 32 KB
#define STGB   (ABYTES + BBYTES)  // 48 KB
#define SMEMSZ (1024 + 2 * STGB)

// ---------------- scratch (device globals; no allocs) ----------------
__device__ __align__(16) __nv_bfloat16 g_Tb[(size_t)NTGT * KTOT];   //  8.4 MB
__device__ __align__(16) float g_D[SPLITK][(size_t)MROWS * NTGT];   // 17.2 MB
__device__ float g_rsumP[SPLITK][MROWS];   // partial rowsums: [0..1199] softplus, [1200..] sigmoid
__device__ float g_tsum4[NTGT * 4];

// ---------------- PTX helpers ----------------
__device__ __forceinline__ uint32_t smem_u32(const void* p) {
    uint32_t a;
    asm("{ .reg .u64 t; cvta.to.shared.u64 t, %1; cvt.u32.u64 %0, t; }" : "=r"(a) : "l"(p));
    return a;
}
__device__ __forceinline__ void cp16(uint32_t sdst, const void* src) {
    asm volatile("cp.async.cg.shared.global [%0], [%1], 16;\n" ::"r"(sdst), "l"(src));
}
__device__ __forceinline__ void ldsm4(uint32_t* r, uint32_t addr) {
    asm volatile("ldmatrix.sync.aligned.m8n8.x4.shared.b16 {%0,%1,%2,%3}, [%4];"
                 : "=r"(r[0]), "=r"(r[1]), "=r"(r[2]), "=r"(r[3]) : "r"(addr));
}
__device__ __forceinline__ void sts16(uint32_t addr, const uint32_t* v) {
    asm volatile("st.shared.v4.b32 [%0], {%1,%2,%3,%4};"
                 ::"r"(addr), "r"(v[0]), "r"(v[1]), "r"(v[2]), "r"(v[3]) : "memory");
}
__device__ __forceinline__ void mma16816(float* d, const uint32_t* a, const uint32_t* b) {
    asm volatile(
        "mma.sync.aligned.m16n8k16.row.col.f32.bf16.bf16.f32 "
        "{%0,%1,%2,%3}, {%4,%5,%6,%7}, {%8,%9}, {%0,%1,%2,%3};\n"
        : "+f"(d[0]), "+f"(d[1]), "+f"(d[2]), "+f"(d[3])
        : "r"(a[0]), "r"(a[1]), "r"(a[2]), "r"(a[3]), "r"(b[0]), "r"(b[1]));
}

template <int NW>
__device__ __forceinline__ float block_sum(float v) {
    __shared__ float red[NW];
    int lane = threadIdx.x & 31, w = threadIdx.x >> 5;
#pragma unroll
    for (int o = 16; o > 0; o >>= 1) v += __shfl_down_sync(0xffffffffu, v, o);
    if (lane == 0) red[w] = v;
    __syncthreads();
    if (w == 0) {
        v = (lane < NW) ? red[lane] : 0.f;
#pragma unroll
        for (int o = NW / 2; o > 0; o >>= 1) v += __shfl_down_sync(0xffffffffu, v, o);
    }
    return v;  // valid on thread 0
}

// jax.image.resize(antialias=True) 2x-down triangle taps, edge-renormalized.
__device__ __forceinline__ void make_taps(int i, int* j, float* w) {
    const float bw[4] = {0.125f, 0.375f, 0.375f, 0.125f};
    float s = 0.f;
#pragma unroll
    for (int d = 0; d < 4; ++d) {
        int jj = 2 * i - 1 + d;
        bool ok = (jj >= 0) && (jj < SRC);
        j[d] = ok ? jj : 0;
        w[d] = ok ? bw[d] : 0.f;
        s += w[d];
    }
    float inv = 1.f / s;
#pragma unroll
    for (int d = 0; d < 4; ++d) w[d] *= inv;
}

// ---------------- kernel 1: resize targets 256x256 -> 128x128 (bf16) + tsum ----------------
__global__ __launch_bounds__(128) void k_resize(const float* __restrict__ tgt) {
    int m = blockIdx.x;
    int chunk = blockIdx.y;   // 4 row-chunks of 32
    int x = threadIdx.x;
    const float* src = tgt + (size_t)m * (SRC * SRC);
    __nv_bfloat16* dst = g_Tb + (size_t)m * PIX;

    int jx[4]; float wx[4];
    make_taps(x, jx, wx);

    float sum = 0.f;
    int y0 = chunk * 32;
    for (int y = y0; y < y0 + 32; ++y) {
        int jy[4]; float wy[4];
        make_taps(y, jy, wy);
        float v = 0.f;
#pragma unroll
        for (int dy = 0; dy < 4; ++dy) {
            const float* row = src + (size_t)jy[dy] * SRC;
            float h = wx[0] * row[jx[0]] + wx[1] * row[jx[1]] +
                      wx[2] * row[jx[2]] + wx[3] * row[jx[3]];
            v += wy[dy] * h;
        }
        dst[y * HW + x] = __float2bfloat16_rn(v);
        sum += v;
    }
    float tot = block_sum<4>(sum);
    if (threadIdx.x == 0) g_tsum4[m * 4 + chunk] = tot;
}

// ---------------- kernel 2: fused convert + GEMM ----------------
// D[kz] = A(128 rows x Ksplit) @ T^T(256 x Ksplit); A rows generated on the fly
// from pred_masks: row<1200 -> X (raw logits), row>=1200 -> sigmoid(X).
// Also emits per-(kz,row) partial rowsums (softplus for X rows, sigmoid for sig rows).
__global__ __launch_bounds__(256, 1) void k_gemm(const float* __restrict__ pm) {
    extern __shared__ char smem[];
    const uint32_t tiles = (smem_u32(smem) + 1023u) & ~1023u;

    const int tid = threadIdx.x;
    const int lane = tid & 31;
    const int wid = tid >> 5;
    const int wm = wid & 1;    // 2 warp-rows of 64
    const int wn = wid >> 1;   // 4 warp-cols of 64
    const int m0 = blockIdx.x * BM;
    const int kz = blockIdx.y;
    const int t0 = (kz * NKT) / SPLITK;
    const int t1 = ((kz + 1) * NKT) / SPLITK;
    const int NT = t1 - t0;           // 36 or 37
    const int kbase = t0 * BK;        // element offset into K

    // per-thread A-chunk geometry (constant over k-tiles): 4 chunks of 16B (8 bf16)
    int arows[4]; bool avalid[4]; bool aisX[4]; const float* asrc[4]; uint32_t asmoff[4];
#pragma unroll
    for (int i = 0; i < 4; ++i) {
        int idx = tid + (i << 8);
        int row = idx >> 3, c16 = idx & 7;
        int grow = m0 + row;
        avalid[i] = grow < MROWS;
        aisX[i] = grow < NPRED;
        int srow = aisX[i] ? grow : grow - NPRED;
        arows[i] = grow;
        asrc[i] = pm + (size_t)(avalid[i] ? srow : 0) * PIX + kbase + c16 * 8;
        asmoff[i] = (uint32_t)(row * 128 + ((c16 * 16) ^ ((row & 7) << 4)));
    }
    float rs[4] = {0.f, 0.f, 0.f, 0.f};

    uint32_t pk[4][4];
    auto ldgA = [&](int j) {
        int koff = j * BK;
#pragma unroll
        for (int i = 0; i < 4; ++i) {
            const float4* s = (const float4*)(asrc[i] + koff);
            float4 v0, v1;
            if (avalid[i]) { v0 = s[0]; v1 = s[1]; }
            else { v0 = make_float4(0.f, 0.f, 0.f, 0.f); v1 = v0; }
            float xs[8] = {v0.x, v0.y, v0.z, v0.w, v1.x, v1.y, v1.z, v1.w};
            if (aisX[i]) {
#pragma unroll
                for (int c = 0; c < 8; ++c)
                    rs[i] += fmaxf(xs[c], 0.f) + __logf(1.f + __expf(-fabsf(xs[c])));
                __nv_bfloat162 p0 = __floats2bfloat162_rn(xs[0], xs[1]);
                __nv_bfloat162 p1 = __floats2bfloat162_rn(xs[2], xs[3]);
                __nv_bfloat162 p2 = __floats2bfloat162_rn(xs[4], xs[5]);
                __nv_bfloat162 p3 = __floats2bfloat162_rn(xs[6], xs[7]);
                pk[i][0] = *(uint32_t*)&p0; pk[i][1] = *(uint32_t*)&p1;
                pk[i][2] = *(uint32_t*)&p2; pk[i][3] = *(uint32_t*)&p3;
            } else {
                float sg[8];
#pragma unroll
                for (int c = 0; c < 8; ++c) {
                    sg[c] = 1.f / (1.f + __expf(-xs[c]));
                    rs[i] += sg[c];
                }
                __nv_bfloat162 p0 = __floats2bfloat162_rn(sg[0], sg[1]);
                __nv_bfloat162 p1 = __floats2bfloat162_rn(sg[2], sg[3]);
                __nv_bfloat162 p2 = __floats2bfloat162_rn(sg[4], sg[5]);
                __nv_bfloat162 p3 = __floats2bfloat162_rn(sg[6], sg[7]);
                pk[i][0] = *(uint32_t*)&p0; pk[i][1] = *(uint32_t*)&p1;
                pk[i][2] = *(uint32_t*)&p2; pk[i][3] = *(uint32_t*)&p3;
            }
        }
    };
    auto stsA = [&](int j) {
        uint32_t ab = tiles + (j & 1) * STGB;
#pragma unroll
        for (int i = 0; i < 4; ++i) sts16(ab + asmoff[i], pk[i]);
    };
    auto cpB = [&](int j) {
        uint32_t bb = tiles + (j & 1) * STGB + ABYTES;
        int k0 = kbase + j * BK;
#pragma unroll
        for (int i = 0; i < 8; ++i) {
            int idx = tid + (i << 8);
            int row = idx >> 3, c16 = idx & 7;
            const void* src = g_Tb + (size_t)row * KTOT + k0 + c16 * 8;
            uint32_t off = (uint32_t)(row * 128 + ((c16 * 16) ^ ((row & 7) << 4)));
            cp16(bb + off, src);
        }
        asm volatile("cp.async.commit_group;\n" ::: "memory");
    };

    // per-thread ldmatrix bases
    const int arow = wm * 64 + (lane & 7) + (lane & 8);
    const uint32_t acol0 = (uint32_t)(((lane >> 4) & 1) * 16);
    const int brow0 = wn * 64 + (lane & 7) + ((lane >> 1) & 8);
    const uint32_t bcol0 = (uint32_t)((lane & 8) * 2);

    float acc[4][8][4];
#pragma unroll
    for (int a = 0; a < 4; ++a)
#pragma unroll
        for (int b = 0; b < 8; ++b)
#pragma unroll
            for (int c = 0; c < 4; ++c) acc[a][b][c] = 0.f;

    // prologue: fill both stages
    ldgA(0); stsA(0); cpB(0);
    ldgA(1); stsA(1); cpB(1);

#pragma unroll 1
    for (int kt = 0; kt < NT; ++kt) {
        if (kt < NT - 1) {
            asm volatile("cp.async.wait_group 1;\n" ::: "memory");
        } else {
            asm volatile("cp.async.wait_group 0;\n" ::: "memory");
        }
        __syncthreads();

        int stage = kt & 1;
        uint32_t ab = tiles + stage * STGB;
        uint32_t bb = ab + ABYTES;

#pragma unroll
        for (int kb = 0; kb < 4; ++kb) {
            uint32_t af[4][4], bf[8][2];
            uint32_t acolb = (uint32_t)(kb * 32) + acol0;
            uint32_t bcolb = (uint32_t)(kb * 32) + bcol0;
#pragma unroll
            for (int mb = 0; mb < 4; ++mb) {
                int r = arow + mb * 16;
                ldsm4(af[mb], ab + (uint32_t)(r * 128) + (acolb ^ ((uint32_t)(r & 7) << 4)));
            }
#pragma unroll
            for (int p = 0; p < 4; ++p) {
                int r = brow0 + p * 16;
                uint32_t tmp[4];
                ldsm4(tmp, bb + (uint32_t)(r * 128) + (bcolb ^ ((uint32_t)(r & 7) << 4)));
                bf[2 * p][0] = tmp[0]; bf[2 * p][1] = tmp[1];
                bf[2 * p + 1][0] = tmp[2]; bf[2 * p + 1][1] = tmp[3];
            }
#pragma unroll
            for (int mb = 0; mb < 4; ++mb)
#pragma unroll
                for (int nb = 0; nb < 8; ++nb) mma16816(acc[mb][nb], af[mb], bf[nb]);
        }

        if (kt + 2 < NT) ldgA(kt + 2);
        __syncthreads();
        if (kt + 2 < NT) { stsA(kt + 2); cpB(kt + 2); }
    }

    // rowsum partials: reduce across the 8 consecutive lanes sharing a row
#pragma unroll
    for (int i = 0; i < 4; ++i) {
        float v = rs[i];
        v += __shfl_xor_sync(0xffffffffu, v, 1);
        v += __shfl_xor_sync(0xffffffffu, v, 2);
        v += __shfl_xor_sync(0xffffffffu, v, 4);
        if ((tid & 7) == 0 && avalid[i]) g_rsumP[kz][arows[i]] = v;
    }

    // epilogue
    float* Dp = g_D[kz];
    const int trow = lane >> 2;
    const int tcol = (lane & 3) * 2;
#pragma unroll
    for (int mb = 0; mb < 4; ++mb) {
        int r0 = m0 + wm * 64 + mb * 16 + trow;
        int r1 = r0 + 8;
#pragma unroll
        for (int nb = 0; nb < 8; ++nb) {
            int col = wn * 64 + nb * 8 + tcol;
            if (r0 < MROWS)
                *(float2*)&Dp[(size_t)r0 * NTGT + col] = make_float2(acc[mb][nb][0], acc[mb][nb][1]);
            if (r1 < MROWS)
                *(float2*)&Dp[(size_t)r1 * NTGT + col] = make_float2(acc[mb][nb][2], acc[mb][nb][3]);
        }
    }
}

// ---------------- kernel 3: assemble final cost matrix ----------------
__global__ __launch_bounds__(256) void k_assemble(const float* __restrict__ logits,
                                                  const float* __restrict__ pboxes,
                                                  const int* __restrict__ ids,
                                                  const float* __restrict__ tboxes,
                                                  float* __restrict__ out) {
    int n = blockIdx.x;
    int m = threadIdx.x;

    float4 pb = ((const float4*)pboxes)[n];
    float4 tb = ((const float4*)tboxes)[m];

    float cbbox = fabsf(pb.x - tb.x) + fabsf(pb.y - tb.y) +
                  fabsf(pb.z - tb.z) + fabsf(pb.w - tb.w);

    float p1x = pb.x - 0.5f * pb.z, p1y = pb.y - 0.5f * pb.w;
    float p2x = pb.x + 0.5f * pb.z, p2y = pb.y + 0.5f * pb.w;
    float t1x = tb.x - 0.5f * tb.z, t1y = tb.y - 0.5f * tb.w;
    float t2x = tb.x + 0.5f * tb.z, t2y = tb.y + 0.5f * tb.w;
    float area1 = (p2x - p1x) * (p2y - p1y);
    float area2 = (t2x - t1x) * (t2y - t1y);
    float iw = fmaxf(fminf(p2x, t2x) - fmaxf(p1x, t1x), 0.f);
    float ih = fmaxf(fminf(p2y, t2y) - fmaxf(p1y, t1y), 0.f);
    float inter = iw * ih;
    float uni = area1 + area2 - inter;
    float iou = inter / uni;
    float ew = fmaxf(fmaxf(p2x, t2x) - fminf(p1x, t1x), 0.f);
    float eh = fmaxf(fmaxf(p2y, t2y) - fminf(p1y, t1y), 0.f);
    float ae = ew * eh;
    float cgiou = -(iou - (ae - uni) / ae);

    int id = ids[m];
    float lg = logits[(size_t)n * NCLS + id];
    float cclass = -1.f / (1.f + expf(-lg));

    size_t ix = (size_t)n * NTGT + m;
    size_t is = (size_t)(NPRED + n) * NTGT + m;
    float dX = 0.f, dS = 0.f, ssum = 0.f, sigsum = 0.f;
#pragma unroll
    for (int s = 0; s < SPLITK; ++s) {
        dX += g_D[s][ix];
        dS += g_D[s][is];
        ssum += g_rsumP[s][n];
        sigsum += g_rsumP[s][NPRED + n];
    }

    float tsum = g_tsum4[m * 4] + g_tsum4[m * 4 + 1] + g_tsum4[m * 4 + 2] + g_tsum4[m * 4 + 3];
    float cmask = (ssum - dX) * (1.f / (float)PIX);
    float denom = fmaxf(sigsum + tsum, 1e-6f) + 1.f;
    float cdice = -(2.f * dS + 1.f) / denom;

    out[ix] = 5.f * cbbox + 2.f * cgiou + 2.f * cclass + 2.f * cmask + 2.f * cdice;
}

// ---------------- launch ----------------
extern "C" void kernel_launch(void* const* d_in, const int* in_sizes, int n_in,
                              void* d_out, int out_size) {
    const float* logits = (const float*)d_in[0];
    const float* pboxes = (const float*)d_in[1];
    const float* pmasks = (const float*)d_in[2];
    const int*   ids    = (const int*)d_in[3];
    const float* tboxes = (const float*)d_in[4];
    const float* tmasks = (const float*)d_in[5];
    float* out = (float*)d_out;

    cudaFuncSetAttribute(k_gemm, cudaFuncAttributeMaxDynamicSharedMemorySize, SMEMSZ);

    k_resize<<<dim3(NTGT, 4), 128>>>(tmasks);
    k_gemm<<<dim3(MT, SPLITK), 256, SMEMSZ>>>(pmasks);
    k_assemble<<<NPRED, NTGT>>>(logits, pboxes, ids, tboxes, out);
}

// round 9
// speedup vs baseline: 1.6565x; 1.6565x over previous
#include <cuda_runtime.h>
#include <cuda_bf16.h>
#include <cstdint>

// ---------------- problem constants ----------------
#define NPRED 1200
#define NTGT  256
#define NCLS  80
#define HW    128
#define SRC   256
#define PIX   16384
#define KTOT  16384
#define MROWS 2400      // rows 0..1199: X (logits), 1200..2399: sigmoid(X)

// ---------------- GEMM config (legacy mma.sync bf16, sm_100-safe) ----------------
#define BM     128
#define BN     256
#define BK     64                 // 128B rows in smem
#define SPLITK 7
#define KS     2368               // ceil(16384/7/64)*64 ; last split gets 2176
#define MT     19                 // ceil(2400/128)
#define ABYTES (BM * 128)         // 16 KB
#define BBYTES (BN * 128)         // 32 KB
#define STGB   (ABYTES + BBYTES)  // 48 KB
#define SMEMSZ (1024 + 2 * STGB)

// resize chunking
#define RCH    8                  // output rows per block
#define NCHUNK (HW / RCH)         // 16

// ---------------- scratch (device globals; no allocs) ----------------
__device__ __align__(16) __nv_bfloat16 g_Ab[(size_t)MROWS * KTOT];   // 78.6 MB
__device__ __align__(16) __nv_bfloat16 g_Tb[(size_t)NTGT * KTOT];    //  8.4 MB
__device__ __align__(16) float g_D[SPLITK][(size_t)MROWS * NTGT];    // 17.2 MB
__device__ float g_tsum16[NTGT * NCHUNK];
__device__ float g_ssum[NPRED];
__device__ float g_sigsum[NPRED];

// ---------------- PTX helpers ----------------
__device__ __forceinline__ uint32_t smem_u32(const void* p) {
    uint32_t a;
    asm("{ .reg .u64 t; cvta.to.shared.u64 t, %1; cvt.u32.u64 %0, t; }" : "=r"(a) : "l"(p));
    return a;
}
__device__ __forceinline__ void cp16(uint32_t sdst, const void* src, int nbytes) {
    asm volatile("cp.async.cg.shared.global [%0], [%1], 16, %2;\n"
                 ::"r"(sdst), "l"(src), "r"(nbytes));
}
__device__ __forceinline__ void ldsm4(uint32_t* r, uint32_t addr) {
    asm volatile("ldmatrix.sync.aligned.m8n8.x4.shared.b16 {%0,%1,%2,%3}, [%4];"
                 : "=r"(r[0]), "=r"(r[1]), "=r"(r[2]), "=r"(r[3]) : "r"(addr));
}
__device__ __forceinline__ void mma16816(float* d, const uint32_t* a, const uint32_t* b) {
    asm volatile(
        "mma.sync.aligned.m16n8k16.row.col.f32.bf16.bf16.f32 "
        "{%0,%1,%2,%3}, {%4,%5,%6,%7}, {%8,%9}, {%0,%1,%2,%3};\n"
        : "+f"(d[0]), "+f"(d[1]), "+f"(d[2]), "+f"(d[3])
        : "r"(a[0]), "r"(a[1]), "r"(a[2]), "r"(a[3]), "r"(b[0]), "r"(b[1]));
}

template <int NW>
__device__ __forceinline__ float block_sum(float v) {
    __shared__ float red[NW];
    int lane = threadIdx.x & 31, w = threadIdx.x >> 5;
#pragma unroll
    for (int o = 16; o > 0; o >>= 1) v += __shfl_down_sync(0xffffffffu, v, o);
    if (lane == 0) red[w] = v;
    __syncthreads();
    if (w == 0) {
        v = (lane < NW) ? red[lane] : 0.f;
#pragma unroll
        for (int o = NW / 2; o > 0; o >>= 1) v += __shfl_down_sync(0xffffffffu, v, o);
    }
    return v;  // valid on thread 0
}

// jax.image.resize(antialias=True) 2x-down triangle taps, edge-renormalized.
__device__ __forceinline__ void make_taps(int i, int* j, float* w) {
    const float bw[4] = {0.125f, 0.375f, 0.375f, 0.125f};
    float s = 0.f;
#pragma unroll
    for (int d = 0; d < 4; ++d) {
        int jj = 2 * i - 1 + d;
        bool ok = (jj >= 0) && (jj < SRC);
        j[d] = ok ? jj : 0;
        w[d] = ok ? bw[d] : 0.f;
        s += w[d];
    }
    float inv = 1.f / s;
#pragma unroll
    for (int d = 0; d < 4; ++d) w[d] *= inv;
}

// ---------------- kernel 1: separable two-pass resize (bf16 out) + tsum ----------------
// block = (target m, chunk of RCH=8 output rows); 256 threads.
__global__ __launch_bounds__(256) void k_resize(const float* __restrict__ tgt) {
    __shared__ float raw[2 * RCH + 2][SRC];   // 18 x 256 fp32 = 18 KB
    __shared__ float hbuf[2 * RCH + 2][HW];   // 18 x 128 fp32 =  9 KB

    const int m = blockIdx.x;
    const int chunk = blockIdx.y;
    const int tid = threadIdx.x;
    const int y0 = chunk * RCH;
    const int rbase = 2 * y0 - 1;             // first src row needed
    const float* src = tgt + (size_t)m * (SRC * SRC);
    __nv_bfloat16* dst = g_Tb + (size_t)m * PIX;

    // phase 0: coalesced load of 18 src rows (clamped) into smem
    {
        const int NC4 = (2 * RCH + 2) * (SRC / 4);   // 1152 float4 chunks
        for (int idx = tid; idx < NC4; idx += 256) {
            int r = idx >> 6, c4 = idx & 63;
            int grow = min(max(rbase + r, 0), SRC - 1);
            float4 v = *(const float4*)(src + (size_t)grow * SRC + c4 * 4);
            *(float4*)&raw[r][c4 * 4] = v;
        }
    }
    __syncthreads();

    // phase 1: horizontal 4-tap into hbuf
    {
        const int x = tid & (HW - 1);
        int jx[4]; float wx[4];
        make_taps(x, jx, wx);
        for (int r = tid >> 7; r < 2 * RCH + 2; r += 2) {
            hbuf[r][x] = wx[0] * raw[r][jx[0]] + wx[1] * raw[r][jx[1]] +
                         wx[2] * raw[r][jx[2]] + wx[3] * raw[r][jx[3]];
        }
    }
    __syncthreads();

    // phase 2: vertical 4-tap, write bf16, accumulate sum
    float sum = 0.f;
    {
        const int x = tid & (HW - 1);
        const float bw[4] = {0.125f, 0.375f, 0.375f, 0.125f};
        for (int yy = tid >> 7; yy < RCH; yy += 2) {
            int y = y0 + yy;
            float v = 0.f, s = 0.f;
#pragma unroll
            for (int d = 0; d < 4; ++d) {
                int jj = 2 * y - 1 + d;
                bool ok = (jj >= 0) && (jj < SRC);
                float w = ok ? bw[d] : 0.f;
                int sidx = min(max(jj - rbase, 0), 2 * RCH + 1);
                v += w * hbuf[sidx][x];
                s += w;
            }
            v *= (1.f / s);
            dst[y * HW + x] = __float2bfloat16_rn(v);
            sum += v;
        }
    }
    float tot = block_sum<8>(sum);
    if (tid == 0) g_tsum16[m * NCHUNK + chunk] = tot;
}

// ---------------- kernel 2: pred_masks -> bf16 X & sigmoid(X); rowsums ----------------
__global__ __launch_bounds__(256) void k_convert(const float* __restrict__ pm) {
    for (int n = blockIdx.x; n < NPRED; n += gridDim.x) {
        const float4* src = (const float4*)(pm + (size_t)n * PIX);
        uint32_t* dx = (uint32_t*)(g_Ab + (size_t)n * KTOT);
        uint32_t* ds = (uint32_t*)(g_Ab + (size_t)(NPRED + n) * KTOT);

        float ssum = 0.f, gsum = 0.f;
        for (int i = threadIdx.x; i < PIX / 4; i += 256) {
            float4 v = src[i];
            float xs[4] = {v.x, v.y, v.z, v.w};
            float sg[4];
#pragma unroll
            for (int c = 0; c < 4; ++c) {
                float xv = xs[c];
                sg[c] = 1.f / (1.f + __expf(-xv));
                gsum += sg[c];
                ssum += fmaxf(xv, 0.f) + __logf(1.f + __expf(-fabsf(xv)));  // softplus
            }
            __nv_bfloat162 x01 = __floats2bfloat162_rn(xs[0], xs[1]);
            __nv_bfloat162 x23 = __floats2bfloat162_rn(xs[2], xs[3]);
            __nv_bfloat162 s01 = __floats2bfloat162_rn(sg[0], sg[1]);
            __nv_bfloat162 s23 = __floats2bfloat162_rn(sg[2], sg[3]);
            dx[2 * i]     = *(uint32_t*)&x01;
            dx[2 * i + 1] = *(uint32_t*)&x23;
            ds[2 * i]     = *(uint32_t*)&s01;
            ds[2 * i + 1] = *(uint32_t*)&s23;
        }
        float s_tot = block_sum<8>(ssum);
        __syncthreads();
        float g_tot = block_sum<8>(gsum);
        if (threadIdx.x == 0) {
            g_ssum[n] = s_tot;
            g_sigsum[n] = g_tot;
        }
        __syncthreads();
    }
}

// ---------------- kernel 3: GEMM D[kz] = A(128 x K) @ T^T(256 x K), ldmatrix+mma ----------------
__global__ __launch_bounds__(256, 1) void k_gemm() {
    extern __shared__ char smem[];
    const uint32_t tiles = (smem_u32(smem) + 1023u) & ~1023u;

    const int tid = threadIdx.x;
    const int lane = tid & 31;
    const int wid = tid >> 5;
    const int wm = wid & 1;    // 2 warp-rows of 64
    const int wn = wid >> 1;   // 4 warp-cols of 64
    const int m0 = blockIdx.x * BM;
    const int kz = blockIdx.y;
    const int kbase = kz * KS;
    const int kend = min(kbase + KS, KTOT);
    const int NT = (kend - kbase) / BK;   // 37 or 34

    auto load_tile = [&](int j) {
        int stage = j & 1;
        uint32_t ab = tiles + stage * STGB;
        uint32_t bb = ab + ABYTES;
        int k0 = kbase + j * BK;
#pragma unroll
        for (int i = 0; i < 4; ++i) {
            int idx = tid + (i << 8);
            int row = idx >> 3, c16 = idx & 7;
            int grow = m0 + row;
            const void* src = g_Ab + (size_t)(grow < MROWS ? grow : 0) * KTOT + k0 + c16 * 8;
            uint32_t off = (uint32_t)(row * 128 + ((c16 * 16) ^ ((row & 7) << 4)));
            cp16(ab + off, src, grow < MROWS ? 16 : 0);
        }
#pragma unroll
        for (int i = 0; i < 8; ++i) {
            int idx = tid + (i << 8);
            int row = idx >> 3, c16 = idx & 7;
            const void* src = g_Tb + (size_t)row * KTOT + k0 + c16 * 8;
            uint32_t off = (uint32_t)(row * 128 + ((c16 * 16) ^ ((row & 7) << 4)));
            cp16(bb + off, src, 16);
        }
        asm volatile("cp.async.commit_group;\n" ::: "memory");
    };

    const int arow = wm * 64 + (lane & 7) + (lane & 8);
    const uint32_t acol0 = (uint32_t)(((lane >> 4) & 1) * 16);
    const int brow0 = wn * 64 + (lane & 7) + ((lane >> 1) & 8);
    const uint32_t bcol0 = (uint32_t)((lane & 8) * 2);

    float acc[4][8][4];
#pragma unroll
    for (int a = 0; a < 4; ++a)
#pragma unroll
        for (int b = 0; b < 8; ++b)
#pragma unroll
            for (int c = 0; c < 4; ++c) acc[a][b][c] = 0.f;

    load_tile(0);

#pragma unroll 1
    for (int kt = 0; kt < NT; ++kt) {
        if (kt + 1 < NT) {
            load_tile(kt + 1);
            asm volatile("cp.async.wait_group 1;\n" ::: "memory");
        } else {
            asm volatile("cp.async.wait_group 0;\n" ::: "memory");
        }
        __syncthreads();

        int stage = kt & 1;
        uint32_t ab = tiles + stage * STGB;
        uint32_t bb = ab + ABYTES;

#pragma unroll
        for (int kb = 0; kb < 4; ++kb) {
            uint32_t af[4][4], bf[8][2];
            uint32_t acolb = (uint32_t)(kb * 32) + acol0;
            uint32_t bcolb = (uint32_t)(kb * 32) + bcol0;
#pragma unroll
            for (int mb = 0; mb < 4; ++mb) {
                int r = arow + mb * 16;
                ldsm4(af[mb], ab + (uint32_t)(r * 128) + (acolb ^ ((uint32_t)(r & 7) << 4)));
            }
#pragma unroll
            for (int p = 0; p < 4; ++p) {
                int r = brow0 + p * 16;
                uint32_t tmp[4];
                ldsm4(tmp, bb + (uint32_t)(r * 128) + (bcolb ^ ((uint32_t)(r & 7) << 4)));
                bf[2 * p][0] = tmp[0]; bf[2 * p][1] = tmp[1];
                bf[2 * p + 1][0] = tmp[2]; bf[2 * p + 1][1] = tmp[3];
            }
#pragma unroll
            for (int mb = 0; mb < 4; ++mb)
#pragma unroll
                for (int nb = 0; nb < 8; ++nb) mma16816(acc[mb][nb], af[mb], bf[nb]);
        }
        __syncthreads();
    }

    float* Dp = g_D[kz];
    const int trow = lane >> 2;
    const int tcol = (lane & 3) * 2;
#pragma unroll
    for (int mb = 0; mb < 4; ++mb) {
        int r0 = m0 + wm * 64 + mb * 16 + trow;
        int r1 = r0 + 8;
#pragma unroll
        for (int nb = 0; nb < 8; ++nb) {
            int col = wn * 64 + nb * 8 + tcol;
            if (r0 < MROWS)
                *(float2*)&Dp[(size_t)r0 * NTGT + col] = make_float2(acc[mb][nb][0], acc[mb][nb][1]);
            if (r1 < MROWS)
                *(float2*)&Dp[(size_t)r1 * NTGT + col] = make_float2(acc[mb][nb][2], acc[mb][nb][3]);
        }
    }
}

// ---------------- kernel 4: assemble final cost matrix ----------------
__global__ __launch_bounds__(256) void k_assemble(const float* __restrict__ logits,
                                                  const float* __restrict__ pboxes,
                                                  const int* __restrict__ ids,
                                                  const float* __restrict__ tboxes,
                                                  float* __restrict__ out) {
    int n = blockIdx.x;
    int m = threadIdx.x;

    float4 pb = ((const float4*)pboxes)[n];
    float4 tb = ((const float4*)tboxes)[m];

    float cbbox = fabsf(pb.x - tb.x) + fabsf(pb.y - tb.y) +
                  fabsf(pb.z - tb.z) + fabsf(pb.w - tb.w);

    float p1x = pb.x - 0.5f * pb.z, p1y = pb.y - 0.5f * pb.w;
    float p2x = pb.x + 0.5f * pb.z, p2y = pb.y + 0.5f * pb.w;
    float t1x = tb.x - 0.5f * tb.z, t1y = tb.y - 0.5f * tb.w;
    float t2x = tb.x + 0.5f * tb.z, t2y = tb.y + 0.5f * tb.w;
    float area1 = (p2x - p1x) * (p2y - p1y);
    float area2 = (t2x - t1x) * (t2y - t1y);
    float iw = fmaxf(fminf(p2x, t2x) - fmaxf(p1x, t1x), 0.f);
    float ih = fmaxf(fminf(p2y, t2y) - fmaxf(p1y, t1y), 0.f);
    float inter = iw * ih;
    float uni = area1 + area2 - inter;
    float iou = inter / uni;
    float ew = fmaxf(fmaxf(p2x, t2x) - fminf(p1x, t1x), 0.f);
    float eh = fmaxf(fmaxf(p2y, t2y) - fminf(p1y, t1y), 0.f);
    float ae = ew * eh;
    float cgiou = -(iou - (ae - uni) / ae);

    int id = ids[m];
    float lg = logits[(size_t)n * NCLS + id];
    float cclass = -1.f / (1.f + expf(-lg));

    size_t ix = (size_t)n * NTGT + m;
    size_t is = (size_t)(NPRED + n) * NTGT + m;
    float dX = 0.f, dS = 0.f;
#pragma unroll
    for (int s = 0; s < SPLITK; ++s) {
        dX += g_D[s][ix];
        dS += g_D[s][is];
    }

    float tsum = 0.f;
#pragma unroll
    for (int c = 0; c < NCHUNK; ++c) tsum += g_tsum16[m * NCHUNK + c];
    float cmask = (g_ssum[n] - dX) * (1.f / (float)PIX);
    float denom = fmaxf(g_sigsum[n] + tsum, 1e-6f) + 1.f;
    float cdice = -(2.f * dS + 1.f) / denom;

    out[ix] = 5.f * cbbox + 2.f * cgiou + 2.f * cclass + 2.f * cmask + 2.f * cdice;
}

// ---------------- launch ----------------
extern "C" void kernel_launch(void* const* d_in, const int* in_sizes, int n_in,
                              void* d_out, int out_size) {
    const float* logits = (const float*)d_in[0];
    const float* pboxes = (const float*)d_in[1];
    const float* pmasks = (const float*)d_in[2];
    const int*   ids    = (const int*)d_in[3];
    const float* tboxes = (const float*)d_in[4];
    const float* tmasks = (const float*)d_in[5];
    float* out = (float*)d_out;

    cudaFuncSetAttribute(k_gemm, cudaFuncAttributeMaxDynamicSharedMemorySize, SMEMSZ);

    k_resize<<<dim3(NTGT, NCHUNK), 256>>>(tmasks);
    k_convert<<<1184, 256>>>(pmasks);
    k_gemm<<<dim3(MT, SPLITK), 256, SMEMSZ>>>();
    k_assemble<<<NPRED, NTGT>>>(logits, pboxes, ids, tboxes, out);
}

// round 11
// speedup vs baseline: 1.8969x; 1.1452x over previous
#include <cuda_runtime.h>
#include <cuda_bf16.h>
#include <cstdint>

// ---------------- problem constants ----------------
#define NPRED 1200
#define NTGT  256
#define NCLS  80
#define HW    128
#define SRC   256
#define PIX   16384
#define KTOT  16384
#define MROWS 2400      // rows 0..1199: X (logits), 1200..2399: sigmoid(X)

// ---------------- GEMM config (legacy mma.sync bf16, sm_100-safe) ----------------
#define BM     128
#define BN     256
#define BK     64                 // 128B rows in smem
#define SPLITK 7
#define KS     2368               // ceil(16384/7/64)*64 ; last split gets 2176
#define MT     19                 // ceil(2400/128)
#define STAGES 4
#define ABYTES (BM * 128)         // 16 KB
#define BBYTES (BN * 128)         // 32 KB
#define STGB   (ABYTES + BBYTES)  // 48 KB
#define SMEMSZ (1024 + STAGES * STGB)   // ~193 KB

// resize/convert fused-prep chunking
#define RCH    8                  // output rows per resize block
#define NCHUNK (HW / RCH)         // 16
#define RZBLKS (NTGT * NCHUNK)    // 4096 resize blocks
#define PREPBLKS (RZBLKS + NPRED) // + 1200 convert blocks

// ---------------- scratch (device globals; no allocs) ----------------
__device__ __align__(16) __nv_bfloat16 g_Ab[(size_t)MROWS * KTOT];   // 78.6 MB
__device__ __align__(16) __nv_bfloat16 g_Tb[(size_t)NTGT * KTOT];    //  8.4 MB
__device__ __align__(16) float g_D[SPLITK][(size_t)MROWS * NTGT];    // 17.2 MB
__device__ float g_tsum16[NCHUNK * NTGT];   // chunk-major: [c][m] for coalesced assemble reads
__device__ float g_ssum[NPRED];
__device__ float g_sigsum[NPRED];

// ---------------- PTX helpers ----------------
__device__ __forceinline__ uint32_t smem_u32(const void* p) {
    uint32_t a;
    asm("{ .reg .u64 t; cvta.to.shared.u64 t, %1; cvt.u32.u64 %0, t; }" : "=r"(a) : "l"(p));
    return a;
}
__device__ __forceinline__ void cp16(uint32_t sdst, const void* src, int nbytes) {
    asm volatile("cp.async.cg.shared.global [%0], [%1], 16, %2;\n"
                 ::"r"(sdst), "l"(src), "r"(nbytes));
}
__device__ __forceinline__ void ldsm4(uint32_t* r, uint32_t addr) {
    asm volatile("ldmatrix.sync.aligned.m8n8.x4.shared.b16 {%0,%1,%2,%3}, [%4];"
                 : "=r"(r[0]), "=r"(r[1]), "=r"(r[2]), "=r"(r[3]) : "r"(addr));
}
__device__ __forceinline__ void mma16816(float* d, const uint32_t* a, const uint32_t* b) {
    asm volatile(
        "mma.sync.aligned.m16n8k16.row.col.f32.bf16.bf16.f32 "
        "{%0,%1,%2,%3}, {%4,%5,%6,%7}, {%8,%9}, {%0,%1,%2,%3};\n"
        : "+f"(d[0]), "+f"(d[1]), "+f"(d[2]), "+f"(d[3])
        : "r"(a[0]), "r"(a[1]), "r"(a[2]), "r"(a[3]), "r"(b[0]), "r"(b[1]));
}

template <int NW>
__device__ __forceinline__ float block_sum(float v) {
    __shared__ float red[NW];
    int lane = threadIdx.x & 31, w = threadIdx.x >> 5;
#pragma unroll
    for (int o = 16; o > 0; o >>= 1) v += __shfl_down_sync(0xffffffffu, v, o);
    if (lane == 0) red[w] = v;
    __syncthreads();
    if (w == 0) {
        v = (lane < NW) ? red[lane] : 0.f;
#pragma unroll
        for (int o = NW / 2; o > 0; o >>= 1) v += __shfl_down_sync(0xffffffffu, v, o);
    }
    return v;  // valid on thread 0
}

// jax.image.resize(antialias=True) 2x-down triangle taps, edge-renormalized.
__device__ __forceinline__ void make_taps(int i, int* j, float* w) {
    const float bw[4] = {0.125f, 0.375f, 0.375f, 0.125f};
    float s = 0.f;
#pragma unroll
    for (int d = 0; d < 4; ++d) {
        int jj = 2 * i - 1 + d;
        bool ok = (jj >= 0) && (jj < SRC);
        j[d] = ok ? jj : 0;
        w[d] = ok ? bw[d] : 0.f;
        s += w[d];
    }
    float inv = 1.f / s;
#pragma unroll
    for (int d = 0; d < 4; ++d) w[d] *= inv;
}

// ---------------- kernel 1: fused prep (resize blocks + convert blocks) ----------------
// blocks [0, 4096): separable two-pass resize of target m=b/16, row-chunk b%16.
// blocks [4096, 5296): convert pred row n=b-4096 -> bf16 X & sigmoid(X) + rowsums.
__global__ __launch_bounds__(256) void k_prep(const float* __restrict__ tgt,
                                              const float* __restrict__ pm) {
    __shared__ float raw[2 * RCH + 2][SRC];   // 18 KB (resize path only)
    __shared__ float hbuf[2 * RCH + 2][HW];   //  9 KB

    const int b = blockIdx.x;
    const int tid = threadIdx.x;

    if (b < RZBLKS) {
        // ---------- resize ----------
        const int m = b / NCHUNK;
        const int chunk = b % NCHUNK;
        const int y0 = chunk * RCH;
        const int rbase = 2 * y0 - 1;
        const float* src = tgt + (size_t)m * (SRC * SRC);
        __nv_bfloat16* dst = g_Tb + (size_t)m * PIX;

        {
            const int NC4 = (2 * RCH + 2) * (SRC / 4);   // 1152
            for (int idx = tid; idx < NC4; idx += 256) {
                int r = idx >> 6, c4 = idx & 63;
                int grow = min(max(rbase + r, 0), SRC - 1);
                float4 v = *(const float4*)(src + (size_t)grow * SRC + c4 * 4);
                *(float4*)&raw[r][c4 * 4] = v;
            }
        }
        __syncthreads();

        {
            const int x = tid & (HW - 1);
            int jx[4]; float wx[4];
            make_taps(x, jx, wx);
            for (int r = tid >> 7; r < 2 * RCH + 2; r += 2) {
                hbuf[r][x] = wx[0] * raw[r][jx[0]] + wx[1] * raw[r][jx[1]] +
                             wx[2] * raw[r][jx[2]] + wx[3] * raw[r][jx[3]];
            }
        }
        __syncthreads();

        float sum = 0.f;
        {
            const int x = tid & (HW - 1);
            const float bw[4] = {0.125f, 0.375f, 0.375f, 0.125f};
            for (int yy = tid >> 7; yy < RCH; yy += 2) {
                int y = y0 + yy;
                float v = 0.f, s = 0.f;
#pragma unroll
                for (int d = 0; d < 4; ++d) {
                    int jj = 2 * y - 1 + d;
                    bool ok = (jj >= 0) && (jj < SRC);
                    float w = ok ? bw[d] : 0.f;
                    int sidx = min(max(jj - rbase, 0), 2 * RCH + 1);
                    v += w * hbuf[sidx][x];
                    s += w;
                }
                v *= (1.f / s);
                dst[y * HW + x] = __float2bfloat16_rn(v);
                sum += v;
            }
        }
        float tot = block_sum<8>(sum);
        if (tid == 0) g_tsum16[chunk * NTGT + m] = tot;   // chunk-major
    } else {
        // ---------- convert ----------
        const int n = b - RZBLKS;
        const float4* src = (const float4*)(pm + (size_t)n * PIX);
        uint4* dx = (uint4*)(g_Ab + (size_t)n * KTOT);
        uint4* ds = (uint4*)(g_Ab + (size_t)(NPRED + n) * KTOT);

        float ssum = 0.f, gsum = 0.f;
        for (int i = tid; i < PIX / 8; i += 256) {
            float4 v0 = src[2 * i], v1 = src[2 * i + 1];
            float xs[8] = {v0.x, v0.y, v0.z, v0.w, v1.x, v1.y, v1.z, v1.w};
            float sg[8];
#pragma unroll
            for (int c = 0; c < 8; ++c) {
                float xv = xs[c];
                sg[c] = 1.f / (1.f + __expf(-xv));
                gsum += sg[c];
                ssum += fmaxf(xv, 0.f) + __logf(1.f + __expf(-fabsf(xv)));  // softplus
            }
            __nv_bfloat162 x01 = __floats2bfloat162_rn(xs[0], xs[1]);
            __nv_bfloat162 x23 = __floats2bfloat162_rn(xs[2], xs[3]);
            __nv_bfloat162 x45 = __floats2bfloat162_rn(xs[4], xs[5]);
            __nv_bfloat162 x67 = __floats2bfloat162_rn(xs[6], xs[7]);
            dx[i] = make_uint4(*(uint32_t*)&x01, *(uint32_t*)&x23,
                               *(uint32_t*)&x45, *(uint32_t*)&x67);
            __nv_bfloat162 s01 = __floats2bfloat162_rn(sg[0], sg[1]);
            __nv_bfloat162 s23 = __floats2bfloat162_rn(sg[2], sg[3]);
            __nv_bfloat162 s45 = __floats2bfloat162_rn(sg[4], sg[5]);
            __nv_bfloat162 s67 = __floats2bfloat162_rn(sg[6], sg[7]);
            ds[i] = make_uint4(*(uint32_t*)&s01, *(uint32_t*)&s23,
                               *(uint32_t*)&s45, *(uint32_t*)&s67);
        }
        float s_tot = block_sum<8>(ssum);
        __syncthreads();
        float g_tot = block_sum<8>(gsum);
        if (tid == 0) {
            g_ssum[n] = s_tot;
            g_sigsum[n] = g_tot;
        }
    }
}

// ---------------- kernel 2: GEMM D[kz] = A(128 x K) @ T^T(256 x K), ldmatrix+mma ----------------
// 4-stage cp.async pipeline, load distance 2, ONE barrier per k-tile
// (S=4, d=2: stage collision needs S|d or S|d+1 — neither holds).
__global__ __launch_bounds__(256, 1) void k_gemm() {
    extern __shared__ char smem[];
    const uint32_t tiles = (smem_u32(smem) + 1023u) & ~1023u;

    const int tid = threadIdx.x;
    const int lane = tid & 31;
    const int wid = tid >> 5;
    const int wm = wid & 1;    // 2 warp-rows of 64
    const int wn = wid >> 1;   // 4 warp-cols of 64
    const int m0 = blockIdx.x * BM;
    const int kz = blockIdx.y;
    const int kbase = kz * KS;
    const int kend = min(kbase + KS, KTOT);
    const int NT = (kend - kbase) / BK;   // 37 or 34

    auto load_tile = [&](int j) {
        int stage = j & (STAGES - 1);
        uint32_t ab = tiles + stage * STGB;
        uint32_t bb = ab + ABYTES;
        int k0 = kbase + j * BK;
#pragma unroll
        for (int i = 0; i < 4; ++i) {
            int idx = tid + (i << 8);
            int row = idx >> 3, c16 = idx & 7;
            int grow = m0 + row;
            const void* src = g_Ab + (size_t)(grow < MROWS ? grow : 0) * KTOT + k0 + c16 * 8;
            uint32_t off = (uint32_t)(row * 128 + ((c16 * 16) ^ ((row & 7) << 4)));
            cp16(ab + off, src, grow < MROWS ? 16 : 0);
        }
#pragma unroll
        for (int i = 0; i < 8; ++i) {
            int idx = tid + (i << 8);
            int row = idx >> 3, c16 = idx & 7;
            const void* src = g_Tb + (size_t)row * KTOT + k0 + c16 * 8;
            uint32_t off = (uint32_t)(row * 128 + ((c16 * 16) ^ ((row & 7) << 4)));
            cp16(bb + off, src, 16);
        }
        asm volatile("cp.async.commit_group;\n" ::: "memory");
    };

    const int arow = wm * 64 + (lane & 7) + (lane & 8);
    const uint32_t acol0 = (uint32_t)(((lane >> 4) & 1) * 16);
    const int brow0 = wn * 64 + (lane & 7) + ((lane >> 1) & 8);
    const uint32_t bcol0 = (uint32_t)((lane & 8) * 2);

    float acc[4][8][4];
#pragma unroll
    for (int a = 0; a < 4; ++a)
#pragma unroll
        for (int b = 0; b < 8; ++b)
#pragma unroll
            for (int c = 0; c < 4; ++c) acc[a][b][c] = 0.f;

    load_tile(0);
    load_tile(1);

#pragma unroll 1
    for (int kt = 0; kt < NT; ++kt) {
        if (kt + 1 < NT) {
            asm volatile("cp.async.wait_group 1;\n" ::: "memory");
        } else {
            asm volatile("cp.async.wait_group 0;\n" ::: "memory");
        }
        __syncthreads();
        if (kt + 2 < NT) load_tile(kt + 2);

        int stage = kt & (STAGES - 1);
        uint32_t ab = tiles + stage * STGB;
        uint32_t bb = ab + ABYTES;

#pragma unroll
        for (int kb = 0; kb < 4; ++kb) {
            uint32_t af[4][4], bf[8][2];
            uint32_t acolb = (uint32_t)(kb * 32) + acol0;
            uint32_t bcolb = (uint32_t)(kb * 32) + bcol0;
#pragma unroll
            for (int mb = 0; mb < 4; ++mb) {
                int r = arow + mb * 16;
                ldsm4(af[mb], ab + (uint32_t)(r * 128) + (acolb ^ ((uint32_t)(r & 7) << 4)));
            }
#pragma unroll
            for (int p = 0; p < 4; ++p) {
                int r = brow0 + p * 16;
                uint32_t tmp[4];
                ldsm4(tmp, bb + (uint32_t)(r * 128) + (bcolb ^ ((uint32_t)(r & 7) << 4)));
                bf[2 * p][0] = tmp[0]; bf[2 * p][1] = tmp[1];
                bf[2 * p + 1][0] = tmp[2]; bf[2 * p + 1][1] = tmp[3];
            }
#pragma unroll
            for (int mb = 0; mb < 4; ++mb)
#pragma unroll
                for (int nb = 0; nb < 8; ++nb) mma16816(acc[mb][nb], af[mb], bf[nb]);
        }
    }

    float* Dp = g_D[kz];
    const int trow = lane >> 2;
    const int tcol = (lane & 3) * 2;
#pragma unroll
    for (int mb = 0; mb < 4; ++mb) {
        int r0 = m0 + wm * 64 + mb * 16 + trow;
        int r1 = r0 + 8;
#pragma unroll
        for (int nb = 0; nb < 8; ++nb) {
            int col = wn * 64 + nb * 8 + tcol;
            if (r0 < MROWS)
                *(float2*)&Dp[(size_t)r0 * NTGT + col] = make_float2(acc[mb][nb][0], acc[mb][nb][1]);
            if (r1 < MROWS)
                *(float2*)&Dp[(size_t)r1 * NTGT + col] = make_float2(acc[mb][nb][2], acc[mb][nb][3]);
        }
    }
}

// ---------------- kernel 3: assemble final cost matrix ----------------
__global__ __launch_bounds__(256) void k_assemble(const float* __restrict__ logits,
                                                  const float* __restrict__ pboxes,
                                                  const int* __restrict__ ids,
                                                  const float* __restrict__ tboxes,
                                                  float* __restrict__ out) {
    int n = blockIdx.x;
    int m = threadIdx.x;

    float4 pb = ((const float4*)pboxes)[n];
    float4 tb = ((const float4*)tboxes)[m];

    float cbbox = fabsf(pb.x - tb.x) + fabsf(pb.y - tb.y) +
                  fabsf(pb.z - tb.z) + fabsf(pb.w - tb.w);

    float p1x = pb.x - 0.5f * pb.z, p1y = pb.y - 0.5f * pb.w;
    float p2x = pb.x + 0.5f * pb.z, p2y = pb.y + 0.5f * pb.w;
    float t1x = tb.x - 0.5f * tb.z, t1y = tb.y - 0.5f * tb.w;
    float t2x = tb.x + 0.5f * tb.z, t2y = tb.y + 0.5f * tb.w;
    float area1 = (p2x - p1x) * (p2y - p1y);
    float area2 = (t2x - t1x) * (t2y - t1y);
    float iw = fmaxf(fminf(p2x, t2x) - fmaxf(p1x, t1x), 0.f);
    float ih = fmaxf(fminf(p2y, t2y) - fmaxf(p1y, t1y), 0.f);
    float inter = iw * ih;
    float uni = area1 + area2 - inter;
    float iou = inter / uni;
    float ew = fmaxf(fmaxf(p2x, t2x) - fminf(p1x, t1x), 0.f);
    float eh = fmaxf(fmaxf(p2y, t2y) - fminf(p1y, t1y), 0.f);
    float ae = ew * eh;
    float cgiou = -(iou - (ae - uni) / ae);

    int id = ids[m];
    float lg = logits[(size_t)n * NCLS + id];
    float cclass = -1.f / (1.f + expf(-lg));

    size_t ix = (size_t)n * NTGT + m;
    size_t is = (size_t)(NPRED + n) * NTGT + m;
    float dX = 0.f, dS = 0.f;
#pragma unroll
    for (int s = 0; s < SPLITK; ++s) {
        dX += g_D[s][ix];
        dS += g_D[s][is];
    }

    float tsum = 0.f;
#pragma unroll
    for (int c = 0; c < NCHUNK; ++c) tsum += g_tsum16[c * NTGT + m];   // coalesced
    float cmask = (g_ssum[n] - dX) * (1.f / (float)PIX);
    float denom = fmaxf(g_sigsum[n] + tsum, 1e-6f) + 1.f;
    float cdice = -(2.f * dS + 1.f) / denom;

    out[ix] = 5.f * cbbox + 2.f * cgiou + 2.f * cclass + 2.f * cmask + 2.f * cdice;
}

// ---------------- launch ----------------
extern "C" void kernel_launch(void* const* d_in, const int* in_sizes, int n_in,
                              void* d_out, int out_size) {
    const float* logits = (const float*)d_in[0];
    const float* pboxes = (const float*)d_in[1];
    const float* pmasks = (const float*)d_in[2];
    const int*   ids    = (const int*)d_in[3];
    const float* tboxes = (const float*)d_in[4];
    const float* tmasks = (const float*)d_in[5];
    float* out = (float*)d_out;

    cudaFuncSetAttribute(k_gemm, cudaFuncAttributeMaxDynamicSharedMemorySize, SMEMSZ);

    k_prep<<<PREPBLKS, 256>>>(tmasks, pmasks);
    k_gemm<<<dim3(MT, SPLITK), 256, SMEMSZ>>>();
    k_assemble<<<NPRED, NTGT>>>(logits, pboxes, ids, tboxes, out);
}

// round 13
// speedup vs baseline: 1.9987x; 1.0536x over previous
#include <cuda_runtime.h>
#include <cuda_bf16.h>
#include <cstdint>

// ---------------- problem constants ----------------
#define NPRED 1200
#define NTGT  256
#define NCLS  80
#define HW    128
#define SRC   256
#define PIX   16384
#define KTOT  16384
#define MROWS 2400      // rows 0..1199: X (logits), 1200..2399: sigmoid(X)

// ---------------- GEMM config (legacy mma.sync bf16, sm_100-safe) ----------------
#define BM     128
#define BN     256
#define BK     64                 // 128B rows in smem
#define SPLITK 7
#define KS     2368               // ceil(16384/7/64)*64 ; last split gets 2176
#define MT     19                 // ceil(2400/128)
#define STAGES 4
#define ABYTES (BM * 128)         // 16 KB
#define BBYTES (BN * 128)         // 32 KB
#define STGB   (ABYTES + BBYTES)  // 48 KB
#define SMEMSZ (1024 + STAGES * STGB)   // ~193 KB

// resize/convert fused-prep chunking (convert blocks FIRST: heavier -> LPT)
#define RCH    8                  // output rows per resize block
#define NCHUNK (HW / RCH)         // 16
#define RZBLKS (NTGT * NCHUNK)    // 4096 resize blocks
#define PREPBLKS (RZBLKS + NPRED) // 1200 convert + 4096 resize

// ---------------- scratch (device globals; no allocs) ----------------
__device__ __align__(16) __nv_bfloat16 g_Ab[(size_t)MROWS * KTOT];   // 78.6 MB
__device__ __align__(16) __nv_bfloat16 g_Tb[(size_t)NTGT * KTOT];    //  8.4 MB
__device__ __align__(16) float g_D[SPLITK][(size_t)MROWS * NTGT];    // 17.2 MB
__device__ float g_tsum16[NCHUNK * NTGT];   // chunk-major: [c][m] for coalesced assemble reads
__device__ float g_ssum[NPRED];
__device__ float g_sigsum[NPRED];

// ---------------- PTX helpers ----------------
__device__ __forceinline__ uint32_t smem_u32(const void* p) {
    uint32_t a;
    asm("{ .reg .u64 t; cvta.to.shared.u64 t, %1; cvt.u32.u64 %0, t; }" : "=r"(a) : "l"(p));
    return a;
}
__device__ __forceinline__ void cp16(uint32_t sdst, const void* src, int nbytes) {
    asm volatile("cp.async.cg.shared.global [%0], [%1], 16, %2;\n"
                 ::"r"(sdst), "l"(src), "r"(nbytes));
}
__device__ __forceinline__ void ldsm4(uint32_t* r, uint32_t addr) {
    asm volatile("ldmatrix.sync.aligned.m8n8.x4.shared.b16 {%0,%1,%2,%3}, [%4];"
                 : "=r"(r[0]), "=r"(r[1]), "=r"(r[2]), "=r"(r[3]) : "r"(addr));
}
__device__ __forceinline__ void mma16816(float* d, const uint32_t* a, const uint32_t* b) {
    asm volatile(
        "mma.sync.aligned.m16n8k16.row.col.f32.bf16.bf16.f32 "
        "{%0,%1,%2,%3}, {%4,%5,%6,%7}, {%8,%9}, {%0,%1,%2,%3};\n"
        : "+f"(d[0]), "+f"(d[1]), "+f"(d[2]), "+f"(d[3])
        : "r"(a[0]), "r"(a[1]), "r"(a[2]), "r"(a[3]), "r"(b[0]), "r"(b[1]));
}

template <int NW>
__device__ __forceinline__ float block_sum(float v) {
    __shared__ float red[NW];
    int lane = threadIdx.x & 31, w = threadIdx.x >> 5;
#pragma unroll
    for (int o = 16; o > 0; o >>= 1) v += __shfl_down_sync(0xffffffffu, v, o);
    if (lane == 0) red[w] = v;
    __syncthreads();
    if (w == 0) {
        v = (lane < NW) ? red[lane] : 0.f;
#pragma unroll
        for (int o = NW / 2; o > 0; o >>= 1) v += __shfl_down_sync(0xffffffffu, v, o);
    }
    return v;  // valid on thread 0
}

// jax.image.resize(antialias=True) 2x-down triangle taps, edge-renormalized.
// Edge renorm is exactly 8/7 (only index 0 and 127 lose one 1/8 tap) -> select, no div.
__device__ __forceinline__ void make_taps(int i, int* j, float* w) {
    const float bw[4] = {0.125f, 0.375f, 0.375f, 0.125f};
    const float inv = (i == 0 || i == HW - 1) ? (8.f / 7.f) : 1.f;
#pragma unroll
    for (int d = 0; d < 4; ++d) {
        int jj = 2 * i - 1 + d;
        bool ok = (jj >= 0) && (jj < SRC);
        j[d] = ok ? jj : 0;
        w[d] = (ok ? bw[d] : 0.f) * inv;
    }
}

// ---------------- kernel 1: fused prep (convert blocks first, then resize) ----------------
// blocks [0, 1200): convert pred row n=b -> bf16 X & sigmoid(X) + rowsums.
// blocks [1200, 5296): separable two-pass resize of target m, row-chunk.
__global__ __launch_bounds__(256) void k_prep(const float* __restrict__ tgt,
                                              const float* __restrict__ pm) {
    __shared__ float raw[2 * RCH + 2][SRC];   // 18 KB (resize path only)
    __shared__ float hbuf[2 * RCH + 2][HW];   //  9 KB

    const int b = blockIdx.x;
    const int tid = threadIdx.x;

    if (b < NPRED) {
        // ---------- convert ----------
        const int n = b;
        const float4* src = (const float4*)(pm + (size_t)n * PIX);
        uint4* dx = (uint4*)(g_Ab + (size_t)n * KTOT);
        uint4* ds = (uint4*)(g_Ab + (size_t)(NPRED + n) * KTOT);

        float ssum = 0.f, gsum = 0.f;
        for (int i = tid; i < PIX / 8; i += 256) {
            float4 v0 = src[2 * i], v1 = src[2 * i + 1];
            float xs[8] = {v0.x, v0.y, v0.z, v0.w, v1.x, v1.y, v1.z, v1.w};
            float sg[8];
#pragma unroll
            for (int c = 0; c < 8; ++c) {
                float xv = xs[c];
                float t = __expf(-fabsf(xv));
                float u = __fdividef(1.f, 1.f + t);   // sigmoid(|x|)
                float lg = __logf(u);                 // = -log(1+t)
                sg[c] = (xv >= 0.f) ? u : 1.f - u;    // sigmoid(x)
                gsum += sg[c];
                ssum += fmaxf(xv, 0.f) - lg;          // softplus(x)
            }
            __nv_bfloat162 x01 = __floats2bfloat162_rn(xs[0], xs[1]);
            __nv_bfloat162 x23 = __floats2bfloat162_rn(xs[2], xs[3]);
            __nv_bfloat162 x45 = __floats2bfloat162_rn(xs[4], xs[5]);
            __nv_bfloat162 x67 = __floats2bfloat162_rn(xs[6], xs[7]);
            dx[i] = make_uint4(*(uint32_t*)&x01, *(uint32_t*)&x23,
                               *(uint32_t*)&x45, *(uint32_t*)&x67);
            __nv_bfloat162 s01 = __floats2bfloat162_rn(sg[0], sg[1]);
            __nv_bfloat162 s23 = __floats2bfloat162_rn(sg[2], sg[3]);
            __nv_bfloat162 s45 = __floats2bfloat162_rn(sg[4], sg[5]);
            __nv_bfloat162 s67 = __floats2bfloat162_rn(sg[6], sg[7]);
            ds[i] = make_uint4(*(uint32_t*)&s01, *(uint32_t*)&s23,
                               *(uint32_t*)&s45, *(uint32_t*)&s67);
        }
        float s_tot = block_sum<8>(ssum);
        __syncthreads();
        float g_tot = block_sum<8>(gsum);
        if (tid == 0) {
            g_ssum[n] = s_tot;
            g_sigsum[n] = g_tot;
        }
    } else {
        // ---------- resize ----------
        const int rb = b - NPRED;
        const int m = rb / NCHUNK;
        const int chunk = rb % NCHUNK;
        const int y0 = chunk * RCH;
        const int rbase = 2 * y0 - 1;
        const float* src = tgt + (size_t)m * (SRC * SRC);
        __nv_bfloat16* dst = g_Tb + (size_t)m * PIX;

        {
            const int NC4 = (2 * RCH + 2) * (SRC / 4);   // 1152
            for (int idx = tid; idx < NC4; idx += 256) {
                int r = idx >> 6, c4 = idx & 63;
                int grow = min(max(rbase + r, 0), SRC - 1);
                float4 v = *(const float4*)(src + (size_t)grow * SRC + c4 * 4);
                *(float4*)&raw[r][c4 * 4] = v;
            }
        }
        __syncthreads();

        {
            const int x = tid & (HW - 1);
            int jx[4]; float wx[4];
            make_taps(x, jx, wx);
            for (int r = tid >> 7; r < 2 * RCH + 2; r += 2) {
                hbuf[r][x] = wx[0] * raw[r][jx[0]] + wx[1] * raw[r][jx[1]] +
                             wx[2] * raw[r][jx[2]] + wx[3] * raw[r][jx[3]];
            }
        }
        __syncthreads();

        float sum = 0.f;
        {
            const int x = tid & (HW - 1);
            const float bw[4] = {0.125f, 0.375f, 0.375f, 0.125f};
            for (int yy = tid >> 7; yy < RCH; yy += 2) {
                int y = y0 + yy;
                float v = 0.f;
#pragma unroll
                for (int d = 0; d < 4; ++d) {
                    int jj = 2 * y - 1 + d;
                    bool ok = (jj >= 0) && (jj < SRC);
                    float w = ok ? bw[d] : 0.f;
                    int sidx = min(max(jj - rbase, 0), 2 * RCH + 1);
                    v += w * hbuf[sidx][x];
                }
                v *= (y == 0 || y == HW - 1) ? (8.f / 7.f) : 1.f;   // exact edge renorm
                dst[y * HW + x] = __float2bfloat16_rn(v);
                sum += v;
            }
        }
        float tot = block_sum<8>(sum);
        if (tid == 0) g_tsum16[chunk * NTGT + m] = tot;   // chunk-major
    }
}

// ---------------- kernel 2: GEMM D[kz] = A(128 x K) @ T^T(256 x K), ldmatrix+mma ----------------
// 4-stage cp.async pipeline, load distance 2, ONE barrier per k-tile
// (S=4, d=2: stage collision needs S|d or S|d+1 — neither holds).
__global__ __launch_bounds__(256, 1) void k_gemm() {
    extern __shared__ char smem[];
    const uint32_t tiles = (smem_u32(smem) + 1023u) & ~1023u;

    const int tid = threadIdx.x;
    const int lane = tid & 31;
    const int wid = tid >> 5;
    const int wm = wid & 1;    // 2 warp-rows of 64
    const int wn = wid >> 1;   // 4 warp-cols of 64
    const int m0 = blockIdx.x * BM;
    const int kz = blockIdx.y;
    const int kbase = kz * KS;
    const int kend = min(kbase + KS, KTOT);
    const int NT = (kend - kbase) / BK;   // 37 or 34

    auto load_tile = [&](int j) {
        int stage = j & (STAGES - 1);
        uint32_t ab = tiles + stage * STGB;
        uint32_t bb = ab + ABYTES;
        int k0 = kbase + j * BK;
#pragma unroll
        for (int i = 0; i < 4; ++i) {
            int idx = tid + (i << 8);
            int row = idx >> 3, c16 = idx & 7;
            int grow = m0 + row;
            const void* src = g_Ab + (size_t)(grow < MROWS ? grow : 0) * KTOT + k0 + c16 * 8;
            uint32_t off = (uint32_t)(row * 128 + ((c16 * 16) ^ ((row & 7) << 4)));
            cp16(ab + off, src, grow < MROWS ? 16 : 0);
        }
#pragma unroll
        for (int i = 0; i < 8; ++i) {
            int idx = tid + (i << 8);
            int row = idx >> 3, c16 = idx & 7;
            const void* src = g_Tb + (size_t)row * KTOT + k0 + c16 * 8;
            uint32_t off = (uint32_t)(row * 128 + ((c16 * 16) ^ ((row & 7) << 4)));
            cp16(bb + off, src, 16);
        }
        asm volatile("cp.async.commit_group;\n" ::: "memory");
    };

    const int arow = wm * 64 + (lane & 7) + (lane & 8);
    const uint32_t acol0 = (uint32_t)(((lane >> 4) & 1) * 16);
    const int brow0 = wn * 64 + (lane & 7) + ((lane >> 1) & 8);
    const uint32_t bcol0 = (uint32_t)((lane & 8) * 2);

    float acc[4][8][4];
#pragma unroll
    for (int a = 0; a < 4; ++a)
#pragma unroll
        for (int b = 0; b < 8; ++b)
#pragma unroll
            for (int c = 0; c < 4; ++c) acc[a][b][c] = 0.f;

    load_tile(0);
    load_tile(1);

#pragma unroll 1
    for (int kt = 0; kt < NT; ++kt) {
        if (kt + 1 < NT) {
            asm volatile("cp.async.wait_group 1;\n" ::: "memory");
        } else {
            asm volatile("cp.async.wait_group 0;\n" ::: "memory");
        }
        __syncthreads();
        if (kt + 2 < NT) load_tile(kt + 2);

        int stage = kt & (STAGES - 1);
        uint32_t ab = tiles + stage * STGB;
        uint32_t bb = ab + ABYTES;

#pragma unroll
        for (int kb = 0; kb < 4; ++kb) {
            uint32_t af[4][4], bf[8][2];
            uint32_t acolb = (uint32_t)(kb * 32) + acol0;
            uint32_t bcolb = (uint32_t)(kb * 32) + bcol0;
#pragma unroll
            for (int mb = 0; mb < 4; ++mb) {
                int r = arow + mb * 16;
                ldsm4(af[mb], ab + (uint32_t)(r * 128) + (acolb ^ ((uint32_t)(r & 7) << 4)));
            }
#pragma unroll
            for (int p = 0; p < 4; ++p) {
                int r = brow0 + p * 16;
                uint32_t tmp[4];
                ldsm4(tmp, bb + (uint32_t)(r * 128) + (bcolb ^ ((uint32_t)(r & 7) << 4)));
                bf[2 * p][0] = tmp[0]; bf[2 * p][1] = tmp[1];
                bf[2 * p + 1][0] = tmp[2]; bf[2 * p + 1][1] = tmp[3];
            }
#pragma unroll
            for (int mb = 0; mb < 4; ++mb)
#pragma unroll
                for (int nb = 0; nb < 8; ++nb) mma16816(acc[mb][nb], af[mb], bf[nb]);
        }
    }

    float* Dp = g_D[kz];
    const int trow = lane >> 2;
    const int tcol = (lane & 3) * 2;
#pragma unroll
    for (int mb = 0; mb < 4; ++mb) {
        int r0 = m0 + wm * 64 + mb * 16 + trow;
        int r1 = r0 + 8;
#pragma unroll
        for (int nb = 0; nb < 8; ++nb) {
            int col = wn * 64 + nb * 8 + tcol;
            if (r0 < MROWS)
                *(float2*)&Dp[(size_t)r0 * NTGT + col] = make_float2(acc[mb][nb][0], acc[mb][nb][1]);
            if (r1 < MROWS)
                *(float2*)&Dp[(size_t)r1 * NTGT + col] = make_float2(acc[mb][nb][2], acc[mb][nb][3]);
        }
    }
}

// ---------------- kernel 3: assemble final cost matrix ----------------
__global__ __launch_bounds__(256) void k_assemble(const float* __restrict__ logits,
                                                  const float* __restrict__ pboxes,
                                                  const int* __restrict__ ids,
                                                  const float* __restrict__ tboxes,
                                                  float* __restrict__ out) {
    int n = blockIdx.x;
    int m = threadIdx.x;

    float4 pb = ((const float4*)pboxes)[n];
    float4 tb = ((const float4*)tboxes)[m];

    float cbbox = fabsf(pb.x - tb.x) + fabsf(pb.y - tb.y) +
                  fabsf(pb.z - tb.z) + fabsf(pb.w - tb.w);

    float p1x = pb.x - 0.5f * pb.z, p1y = pb.y - 0.5f * pb.w;
    float p2x = pb.x + 0.5f * pb.z, p2y = pb.y + 0.5f * pb.w;
    float t1x = tb.x - 0.5f * tb.z, t1y = tb.y - 0.5f * tb.w;
    float t2x = tb.x + 0.5f * tb.z, t2y = tb.y + 0.5f * tb.w;
    float area1 = (p2x - p1x) * (p2y - p1y);
    float area2 = (t2x - t1x) * (t2y - t1y);
    float iw = fmaxf(fminf(p2x, t2x) - fmaxf(p1x, t1x), 0.f);
    float ih = fmaxf(fminf(p2y, t2y) - fmaxf(p1y, t1y), 0.f);
    float inter = iw * ih;
    float uni = area1 + area2 - inter;
    float iou = inter / uni;
    float ew = fmaxf(fmaxf(p2x, t2x) - fminf(p1x, t1x), 0.f);
    float eh = fmaxf(fmaxf(p2y, t2y) - fminf(p1y, t1y), 0.f);
    float ae = ew * eh;
    float cgiou = -(iou - (ae - uni) / ae);

    int id = ids[m];
    float lg = logits[(size_t)n * NCLS + id];
    float cclass = -1.f / (1.f + expf(-lg));

    size_t ix = (size_t)n * NTGT + m;
    size_t is = (size_t)(NPRED + n) * NTGT + m;
    float dX = 0.f, dS = 0.f;
#pragma unroll
    for (int s = 0; s < SPLITK; ++s) {
        dX += g_D[s][ix];
        dS += g_D[s][is];
    }

    float tsum = 0.f;
#pragma unroll
    for (int c = 0; c < NCHUNK; ++c) tsum += g_tsum16[c * NTGT + m];   // coalesced
    float cmask = (g_ssum[n] - dX) * (1.f / (float)PIX);
    float denom = fmaxf(g_sigsum[n] + tsum, 1e-6f) + 1.f;
    float cdice = -(2.f * dS + 1.f) / denom;

    out[ix] = 5.f * cbbox + 2.f * cgiou + 2.f * cclass + 2.f * cmask + 2.f * cdice;
}

// ---------------- launch ----------------
extern "C" void kernel_launch(void* const* d_in, const int* in_sizes, int n_in,
                              void* d_out, int out_size) {
    const float* logits = (const float*)d_in[0];
    const float* pboxes = (const float*)d_in[1];
    const float* pmasks = (const float*)d_in[2];
    const int*   ids    = (const int*)d_in[3];
    const float* tboxes = (const float*)d_in[4];
    const float* tmasks = (const float*)d_in[5];
    float* out = (float*)d_out;

    cudaFuncSetAttribute(k_gemm, cudaFuncAttributeMaxDynamicSharedMemorySize, SMEMSZ);

    k_prep<<<PREPBLKS, 256>>>(tmasks, pmasks);
    k_gemm<<<dim3(MT, SPLITK), 256, SMEMSZ>>>();
    k_assemble<<<NPRED, NTGT>>>(logits, pboxes, ids, tboxes, out);
}